// round 2
// baseline (speedup 1.0000x reference)
#include <cuda_runtime.h>
#include <math.h>
#include <float.h>

#define BS 64
#define NA 900
#define NT 600
#define ED 256
#define AD 11
#define NC 10
#define NSEL (NA - NT)          /* 300 */
#define MD  (ED + AD)           /* 267 */
#define SORTN 1024
#define TPB_SORT 512
#define CONF_DECAY 0.6f

// Scratch (no device mallocs allowed)
__device__ int g_src[BS * NA];   // per (b,i): >=0 -> instance row s ; <0 -> cached row -(s+1)
__device__ int g_idx2[BS * NT];  // second top-k indices into 0..NA-1

// ---------------------------------------------------------------------------
// Dtype-agnostic mask read: the reference produces a bool array; the harness
// may materialize it as uint8, int32 or float32. Detect from the byte pattern
// of the first 64 bytes (always within bounds for all three dtypes).
// ---------------------------------------------------------------------------
__device__ __forceinline__ bool read_mask(const void* mp, int b) {
    const unsigned char* u8 = (const unsigned char*)mp;
    bool any_gt1 = false, nonmult4 = false;
    #pragma unroll
    for (int i = 0; i < 64; i++) {
        unsigned char v = u8[i];
        if (v > 1) any_gt1 = true;
        if (v != 0 && (i & 3) != 0) nonmult4 = true;
    }
    if (any_gt1)  return ((const float*)mp)[b] != 0.0f;   // float32 0.0/1.0
    if (nonmult4) return u8[b] != 0;                       // uint8 bool
    return ((const int*)mp)[b] != 0;                       // int32 0/1
}

// ---------------------------------------------------------------------------
// Bitonic sort, descending by key, ascending index on ties (matches lax.top_k)
// ---------------------------------------------------------------------------
__device__ __forceinline__ void bitonic_sort_desc(float* skey, int* sidx, int t) {
    for (int k = 2; k <= SORTN; k <<= 1) {
        for (int j = k >> 1; j > 0; j >>= 1) {
            for (int i = t; i < SORTN; i += TPB_SORT) {
                int ixj = i ^ j;
                if (ixj > i) {
                    float ka = skey[i], kb = skey[ixj];
                    int   ia = sidx[i], ib = sidx[ixj];
                    bool a_gt_b = (ka > kb) || (ka == kb && ia < ib);
                    bool desc = ((i & k) == 0);
                    if (desc ? !a_gt_b : a_gt_b) {
                        skey[i] = kb; skey[ixj] = ka;
                        sidx[i] = ib; sidx[ixj] = ia;
                    }
                }
            }
            __syncthreads();
        }
    }
}

// ---------------------------------------------------------------------------
// Kernel 1: per-batch conf_max, top-300, src mapping, conf_c, top-600
// ---------------------------------------------------------------------------
__global__ __launch_bounds__(TPB_SORT) void topk_kernel(
    const float* __restrict__ conf,      // BS,NA,NC
    const float* __restrict__ prevconf,  // BS,NT
    const void*  __restrict__ mask,      // BS (bool; dtype unknown)
    float* __restrict__ newconf_out)     // BS,NT
{
    __shared__ float skey[SORTN];
    __shared__ int   sidx[SORTN];
    __shared__ float cmax[NA];
    __shared__ int   sel[NSEL];

    const int b = blockIdx.x;
    const int t = threadIdx.x;

    // conf_max over classes
    for (int a = t; a < NA; a += TPB_SORT) {
        const float* p = conf + ((size_t)b * NA + a) * NC;
        float m = p[0];
        #pragma unroll
        for (int c = 1; c < NC; c++) m = fmaxf(m, p[c]);
        cmax[a] = m;
        skey[a] = m;
        sidx[a] = a;
    }
    for (int a = NA + t; a < SORTN; a += TPB_SORT) {
        skey[a] = -FLT_MAX; sidx[a] = 0x7FFFFFFF;
    }
    __syncthreads();

    bitonic_sort_desc(skey, sidx, t);

    for (int i = t; i < NSEL; i += TPB_SORT) sel[i] = sidx[i];
    __syncthreads();

    // source-row mapping for feat/anc (composed select)
    const bool m = read_mask(mask, b);
    for (int i = t; i < NA; i += TPB_SORT) {
        int s;
        if (m) s = (i < NT) ? -(i + 1) : sel[i - NT];
        else   s = i;
        g_src[b * NA + i] = s;
    }
    __syncthreads();

    // conf_c = sigmoid(conf_max); first NT rows max'd with prev*decay
    for (int a = t; a < NA; a += TPB_SORT) {
        float s = 1.0f / (1.0f + expf(-cmax[a]));
        if (a < NT) s = fmaxf(prevconf[b * NT + a] * CONF_DECAY, s);
        skey[a] = s;
        sidx[a] = a;
    }
    for (int a = NA + t; a < SORTN; a += TPB_SORT) {
        skey[a] = -FLT_MAX; sidx[a] = 0x7FFFFFFF;
    }
    __syncthreads();

    bitonic_sort_desc(skey, sidx, t);

    for (int i = t; i < NT; i += TPB_SORT) {
        newconf_out[b * NT + i] = skey[i];
        g_idx2[b * NT + i] = sidx[i];
    }
}

// ---------------------------------------------------------------------------
// Kernel 2: merged = concat(feat, anc, -1)  -> BS*NA*MD floats
// ---------------------------------------------------------------------------
__global__ void merged_kernel(
    const float* __restrict__ inst,   // BS,NA,ED
    const float* __restrict__ anch,   // BS,NA,AD
    const float* __restrict__ cfeat,  // BS,NT,ED
    const float* __restrict__ canch,  // BS,NT,AD
    float* __restrict__ out)
{
    const unsigned total = (unsigned)BS * NA * MD;
    unsigned e = blockIdx.x * blockDim.x + threadIdx.x;
    if (e >= total) return;
    unsigned c   = e % MD;
    unsigned row = e / MD;          // b*NA + i
    unsigned b   = row / NA;
    int s = g_src[row];
    float v;
    if (c < ED) {
        v = (s >= 0) ? inst [((size_t)b * NA + s) * ED + c]
                     : cfeat[((size_t)b * NT + (unsigned)(-s - 1)) * ED + c];
    } else {
        unsigned ac = c - ED;
        v = (s >= 0) ? anch [((size_t)b * NA + s) * AD + ac]
                     : canch[((size_t)b * NT + (unsigned)(-s - 1)) * AD + ac];
    }
    out[e] = v;
}

// ---------------------------------------------------------------------------
// Kernel 3: cf gather, float4 vectorized (row base offsets all 16B-aligned)
// ---------------------------------------------------------------------------
__global__ void cf_kernel(
    const float* __restrict__ inst,
    const float* __restrict__ cfeat,
    float4* __restrict__ out)        // BS*NT*(ED/4) float4
{
    const unsigned total = (unsigned)BS * NT * (ED / 4);
    unsigned e = blockIdx.x * blockDim.x + threadIdx.x;
    if (e >= total) return;
    unsigned c = e & 63;             // ED/4 = 64
    unsigned q = e >> 6;             // b*NT + j
    unsigned b = q / NT;
    int i = g_idx2[q];
    int s = g_src[b * NA + i];
    const float4* src = (s >= 0)
        ? (const float4*)(inst  + ((size_t)b * NA + s) * ED)
        : (const float4*)(cfeat + ((size_t)b * NT + (unsigned)(-s - 1)) * ED);
    out[e] = src[c];
}

// ---------------------------------------------------------------------------
// Kernel 4: ca gather (scalar, tiny)
// ---------------------------------------------------------------------------
__global__ void ca_kernel(
    const float* __restrict__ anch,
    const float* __restrict__ canch,
    float* __restrict__ out)         // BS*NT*AD
{
    const unsigned total = (unsigned)BS * NT * AD;
    unsigned e = blockIdx.x * blockDim.x + threadIdx.x;
    if (e >= total) return;
    unsigned c = e % AD;
    unsigned q = e / AD;             // b*NT + j
    unsigned b = q / NT;
    int i = g_idx2[q];
    int s = g_src[b * NA + i];
    out[e] = (s >= 0)
        ? anch [((size_t)b * NA + s) * AD + c]
        : canch[((size_t)b * NT + (unsigned)(-s - 1)) * AD + c];
}

// ---------------------------------------------------------------------------
extern "C" void kernel_launch(void* const* d_in, const int* in_sizes, int n_in,
                              void* d_out, int out_size)
{
    const float* inst  = (const float*)d_in[0];
    const float* anch  = (const float*)d_in[1];
    const float* conf  = (const float*)d_in[2];
    const float* cfeat = (const float*)d_in[3];
    const float* canch = (const float*)d_in[4];
    const float* prevc = (const float*)d_in[5];
    const void*  mask  = (const void*)d_in[6];

    float* out     = (float*)d_out;
    float* merged  = out;                                      // BS*NA*MD
    float* newconf = merged + (size_t)BS * NA * MD;            // BS*NT
    float* cf      = newconf + (size_t)BS * NT;                // BS*NT*ED
    float* ca      = cf + (size_t)BS * NT * ED;                // BS*NT*AD

    topk_kernel<<<BS, TPB_SORT>>>(conf, prevc, mask, newconf);

    {
        unsigned total = (unsigned)BS * NA * MD;
        merged_kernel<<<(total + 255) / 256, 256>>>(inst, anch, cfeat, canch, merged);
    }
    {
        unsigned total = (unsigned)BS * NT * (ED / 4);
        cf_kernel<<<(total + 255) / 256, 256>>>(inst, cfeat, (float4*)cf);
    }
    {
        unsigned total = (unsigned)BS * NT * AD;
        ca_kernel<<<(total + 255) / 256, 256>>>(anch, canch, ca);
    }
}

// round 3
// speedup vs baseline: 1.0030x; 1.0030x over previous
#include <cuda_runtime.h>
#include <math.h>
#include <float.h>

#define BS 64
#define NA 900
#define NT 600
#define ED 256
#define AD 11
#define NC 10
#define NSEL (NA - NT)          /* 300 */
#define MD  (ED + AD)           /* 267 */
#define SORTN 1024
#define TPB_SORT 512
#define CONF_DECAY 0.6f

// Scratch (no device mallocs allowed)
__device__ int g_src[BS * NA];   // per (b,i): >=0 -> instance row s ; <0 -> cached row -(s+1)
__device__ int g_idx2[BS * NT];  // second top-k indices into 0..NA-1

// ---------------------------------------------------------------------------
// Dtype-agnostic mask read: the reference produces a bool array; the harness
// may materialize it as uint8, int32 or float32. Detect from the byte pattern
// of the first 64 bytes (always within bounds for all three dtypes).
// ---------------------------------------------------------------------------
__device__ __forceinline__ bool read_mask(const void* mp, int b) {
    const unsigned char* u8 = (const unsigned char*)mp;
    bool any_gt1 = false, nonmult4 = false;
    #pragma unroll
    for (int i = 0; i < 64; i++) {
        unsigned char v = u8[i];
        if (v > 1) any_gt1 = true;
        if (v != 0 && (i & 3) != 0) nonmult4 = true;
    }
    if (any_gt1)  return ((const float*)mp)[b] != 0.0f;   // float32 0.0/1.0
    if (nonmult4) return u8[b] != 0;                       // uint8 bool
    return ((const int*)mp)[b] != 0;                       // int32 0/1
}

// ---------------------------------------------------------------------------
// Bitonic sort, descending by key, ascending index on ties (matches lax.top_k)
// ---------------------------------------------------------------------------
__device__ __forceinline__ void bitonic_sort_desc(float* skey, int* sidx, int t) {
    for (int k = 2; k <= SORTN; k <<= 1) {
        for (int j = k >> 1; j > 0; j >>= 1) {
            for (int i = t; i < SORTN; i += TPB_SORT) {
                int ixj = i ^ j;
                if (ixj > i) {
                    float ka = skey[i], kb = skey[ixj];
                    int   ia = sidx[i], ib = sidx[ixj];
                    bool a_gt_b = (ka > kb) || (ka == kb && ia < ib);
                    bool desc = ((i & k) == 0);
                    if (desc ? !a_gt_b : a_gt_b) {
                        skey[i] = kb; skey[ixj] = ka;
                        sidx[i] = ib; sidx[ixj] = ia;
                    }
                }
            }
            __syncthreads();
        }
    }
}

// ---------------------------------------------------------------------------
// Kernel 1: per-batch conf_max, top-300, src mapping, conf_c, top-600
// ---------------------------------------------------------------------------
__global__ __launch_bounds__(TPB_SORT) void topk_kernel(
    const float* __restrict__ conf,      // BS,NA,NC
    const float* __restrict__ prevconf,  // BS,NT
    const void*  __restrict__ mask,      // BS (bool; dtype unknown)
    float* __restrict__ newconf_out)     // BS,NT
{
    __shared__ float skey[SORTN];
    __shared__ int   sidx[SORTN];
    __shared__ float cmax[NA];
    __shared__ int   sel[NSEL];

    const int b = blockIdx.x;
    const int t = threadIdx.x;

    // conf_max over classes
    for (int a = t; a < NA; a += TPB_SORT) {
        const float* p = conf + ((size_t)b * NA + a) * NC;
        float m = p[0];
        #pragma unroll
        for (int c = 1; c < NC; c++) m = fmaxf(m, p[c]);
        cmax[a] = m;
        skey[a] = m;
        sidx[a] = a;
    }
    for (int a = NA + t; a < SORTN; a += TPB_SORT) {
        skey[a] = -FLT_MAX; sidx[a] = 0x7FFFFFFF;
    }
    __syncthreads();

    bitonic_sort_desc(skey, sidx, t);

    for (int i = t; i < NSEL; i += TPB_SORT) sel[i] = sidx[i];
    __syncthreads();

    // source-row mapping for feat/anc (composed select)
    const bool m = read_mask(mask, b);
    for (int i = t; i < NA; i += TPB_SORT) {
        int s;
        if (m) s = (i < NT) ? -(i + 1) : sel[i - NT];
        else   s = i;
        g_src[b * NA + i] = s;
    }
    __syncthreads();

    // conf_c = sigmoid(conf_max); first NT rows max'd with prev*decay
    for (int a = t; a < NA; a += TPB_SORT) {
        float s = 1.0f / (1.0f + expf(-cmax[a]));
        if (a < NT) s = fmaxf(prevconf[b * NT + a] * CONF_DECAY, s);
        skey[a] = s;
        sidx[a] = a;
    }
    for (int a = NA + t; a < SORTN; a += TPB_SORT) {
        skey[a] = -FLT_MAX; sidx[a] = 0x7FFFFFFF;
    }
    __syncthreads();

    bitonic_sort_desc(skey, sidx, t);

    for (int i = t; i < NT; i += TPB_SORT) {
        newconf_out[b * NT + i] = skey[i];
        g_idx2[b * NT + i] = sidx[i];
    }
}

// ---------------------------------------------------------------------------
// Kernel 2: merged = concat(feat, anc, -1)  -> BS*NA*MD floats
// ---------------------------------------------------------------------------
__global__ void merged_kernel(
    const float* __restrict__ inst,   // BS,NA,ED
    const float* __restrict__ anch,   // BS,NA,AD
    const float* __restrict__ cfeat,  // BS,NT,ED
    const float* __restrict__ canch,  // BS,NT,AD
    float* __restrict__ out)
{
    const unsigned total = (unsigned)BS * NA * MD;
    unsigned e = blockIdx.x * blockDim.x + threadIdx.x;
    if (e >= total) return;
    unsigned c   = e % MD;
    unsigned row = e / MD;          // b*NA + i
    unsigned b   = row / NA;
    int s = g_src[row];
    float v;
    if (c < ED) {
        v = (s >= 0) ? inst [((size_t)b * NA + s) * ED + c]
                     : cfeat[((size_t)b * NT + (unsigned)(-s - 1)) * ED + c];
    } else {
        unsigned ac = c - ED;
        v = (s >= 0) ? anch [((size_t)b * NA + s) * AD + ac]
                     : canch[((size_t)b * NT + (unsigned)(-s - 1)) * AD + ac];
    }
    out[e] = v;
}

// ---------------------------------------------------------------------------
// Kernel 3: cf gather, float4 vectorized (row base offsets all 16B-aligned)
// ---------------------------------------------------------------------------
__global__ void cf_kernel(
    const float* __restrict__ inst,
    const float* __restrict__ cfeat,
    float4* __restrict__ out)        // BS*NT*(ED/4) float4
{
    const unsigned total = (unsigned)BS * NT * (ED / 4);
    unsigned e = blockIdx.x * blockDim.x + threadIdx.x;
    if (e >= total) return;
    unsigned c = e & 63;             // ED/4 = 64
    unsigned q = e >> 6;             // b*NT + j
    unsigned b = q / NT;
    int i = g_idx2[q];
    int s = g_src[b * NA + i];
    const float4* src = (s >= 0)
        ? (const float4*)(inst  + ((size_t)b * NA + s) * ED)
        : (const float4*)(cfeat + ((size_t)b * NT + (unsigned)(-s - 1)) * ED);
    out[e] = src[c];
}

// ---------------------------------------------------------------------------
// Kernel 4: ca gather (scalar, tiny)
// ---------------------------------------------------------------------------
__global__ void ca_kernel(
    const float* __restrict__ anch,
    const float* __restrict__ canch,
    float* __restrict__ out)         // BS*NT*AD
{
    const unsigned total = (unsigned)BS * NT * AD;
    unsigned e = blockIdx.x * blockDim.x + threadIdx.x;
    if (e >= total) return;
    unsigned c = e % AD;
    unsigned q = e / AD;             // b*NT + j
    unsigned b = q / NT;
    int i = g_idx2[q];
    int s = g_src[b * NA + i];
    out[e] = (s >= 0)
        ? anch [((size_t)b * NA + s) * AD + c]
        : canch[((size_t)b * NT + (unsigned)(-s - 1)) * AD + c];
}

// ---------------------------------------------------------------------------
extern "C" void kernel_launch(void* const* d_in, const int* in_sizes, int n_in,
                              void* d_out, int out_size)
{
    const float* inst  = (const float*)d_in[0];
    const float* anch  = (const float*)d_in[1];
    const float* conf  = (const float*)d_in[2];
    const float* cfeat = (const float*)d_in[3];
    const float* canch = (const float*)d_in[4];
    const float* prevc = (const float*)d_in[5];
    const void*  mask  = (const void*)d_in[6];

    float* out     = (float*)d_out;
    float* merged  = out;                                      // BS*NA*MD
    float* newconf = merged + (size_t)BS * NA * MD;            // BS*NT
    float* cf      = newconf + (size_t)BS * NT;                // BS*NT*ED
    float* ca      = cf + (size_t)BS * NT * ED;                // BS*NT*AD

    topk_kernel<<<BS, TPB_SORT>>>(conf, prevc, mask, newconf);

    {
        unsigned total = (unsigned)BS * NA * MD;
        merged_kernel<<<(total + 255) / 256, 256>>>(inst, anch, cfeat, canch, merged);
    }
    {
        unsigned total = (unsigned)BS * NT * (ED / 4);
        cf_kernel<<<(total + 255) / 256, 256>>>(inst, cfeat, (float4*)cf);
    }
    {
        unsigned total = (unsigned)BS * NT * AD;
        ca_kernel<<<(total + 255) / 256, 256>>>(anch, canch, ca);
    }
}

// round 4
// speedup vs baseline: 1.7991x; 1.7938x over previous
#include <cuda_runtime.h>
#include <math.h>
#include <float.h>

#define BS 64
#define NA 900
#define NT 600
#define ED 256
#define AD 11
#define NC 10
#define NSEL (NA - NT)          /* 300 */
#define MD  (ED + AD)           /* 267 */
#define SORTN 1024
#define TPB_SORT 1024
#define CONF_DECAY 0.6f

#define MROWS (BS * NA)          /* 57600 merged rows  */
#define QROWS (BS * NT)          /* 38400 cf/ca rows   */
#define TOTROWS (MROWS + QROWS)  /* 96000 warps        */

// Scratch (no device mallocs allowed)
__device__ int g_src[BS * NA];   // per (b,i): >=0 -> instance row s ; <0 -> cached row -(s+1)
__device__ int g_idx2[BS * NT];  // second top-k indices into 0..NA-1

// ---------------------------------------------------------------------------
// Dtype-agnostic mask read (bool may arrive as uint8 / int32 / float32)
// ---------------------------------------------------------------------------
__device__ __forceinline__ bool read_mask(const void* mp, int b) {
    const unsigned char* u8 = (const unsigned char*)mp;
    bool any_gt1 = false, nonmult4 = false;
    #pragma unroll
    for (int i = 0; i < 64; i++) {
        unsigned char v = u8[i];
        if (v > 1) any_gt1 = true;
        if (v != 0 && (i & 3) != 0) nonmult4 = true;
    }
    if (any_gt1)  return ((const float*)mp)[b] != 0.0f;
    if (nonmult4) return u8[b] != 0;
    return ((const int*)mp)[b] != 0;
}

// ---------------------------------------------------------------------------
// Order-preserving float <-> uint transform + (key, idx) u64 packing.
// Descending sort on the packed word == descending key, ascending index ties
// (exactly jax.lax.top_k semantics).
// ---------------------------------------------------------------------------
__device__ __forceinline__ unsigned int ord_of_float(float f) {
    unsigned int u = __float_as_uint(f);
    return (u & 0x80000000u) ? ~u : (u | 0x80000000u);
}
__device__ __forceinline__ float float_of_ord(unsigned int o) {
    unsigned int u = (o & 0x80000000u) ? (o ^ 0x80000000u) : ~o;
    return __uint_as_float(u);
}
__device__ __forceinline__ unsigned long long pack_ki(float k, int idx) {
    return ((unsigned long long)ord_of_float(k) << 32)
         | (unsigned long long)(0xFFFFFFFFu - (unsigned)idx);
}

// ---------------------------------------------------------------------------
// Kernel 1: per-batch conf_max, top-300, src mapping, conf_c, top-600.
// 1024 threads, one element per thread, packed-u64 bitonic sort.
// ---------------------------------------------------------------------------
__global__ __launch_bounds__(TPB_SORT) void topk_kernel(
    const float* __restrict__ conf,      // BS,NA,NC
    const float* __restrict__ prevconf,  // BS,NT
    const void*  __restrict__ mask,      // BS (bool; dtype unknown)
    float* __restrict__ newconf_out)     // BS,NT
{
    __shared__ unsigned long long sk[SORTN];
    __shared__ float cmax[NA];
    __shared__ int   sel[NSEL];

    const int b = blockIdx.x;
    const int t = threadIdx.x;

    // conf_max over classes
    if (t < NA) {
        const float* p = conf + ((size_t)b * NA + t) * NC;
        float m = p[0];
        #pragma unroll
        for (int c = 1; c < NC; c++) m = fmaxf(m, p[c]);
        cmax[t] = m;
        sk[t] = pack_ki(m, t);
    } else {
        sk[t] = 0ULL;   // below every real entry
    }
    __syncthreads();

    // bitonic, descending
    #pragma unroll 1
    for (int k = 2; k <= SORTN; k <<= 1) {
        #pragma unroll 1
        for (int j = k >> 1; j > 0; j >>= 1) {
            int ixj = t ^ j;
            if (ixj > t) {
                unsigned long long a = sk[t], c = sk[ixj];
                bool desc = ((t & k) == 0);
                if (desc ? (a < c) : (a > c)) { sk[t] = c; sk[ixj] = a; }
            }
            __syncthreads();
        }
    }

    if (t < NSEL) sel[t] = (int)(0xFFFFFFFFu - (unsigned)(sk[t] & 0xFFFFFFFFu));
    __syncthreads();

    // source-row mapping for feat/anc
    const bool m = read_mask(mask, b);
    if (t < NA) {
        int s;
        if (m) s = (t < NT) ? -(t + 1) : sel[t - NT];
        else   s = t;
        g_src[b * NA + t] = s;
    }

    // conf_c = sigmoid(conf_max); first NT rows max'd with prev*decay
    if (t < NA) {
        float s = 1.0f / (1.0f + expf(-cmax[t]));
        if (t < NT) s = fmaxf(prevconf[b * NT + t] * CONF_DECAY, s);
        sk[t] = pack_ki(s, t);
    } else {
        sk[t] = 0ULL;
    }
    __syncthreads();

    #pragma unroll 1
    for (int k = 2; k <= SORTN; k <<= 1) {
        #pragma unroll 1
        for (int j = k >> 1; j > 0; j >>= 1) {
            int ixj = t ^ j;
            if (ixj > t) {
                unsigned long long a = sk[t], c = sk[ixj];
                bool desc = ((t & k) == 0);
                if (desc ? (a < c) : (a > c)) { sk[t] = c; sk[ixj] = a; }
            }
            __syncthreads();
        }
    }

    if (t < NT) {
        unsigned long long v = sk[t];
        newconf_out[b * NT + t] = float_of_ord((unsigned)(v >> 32));
        g_idx2[b * NT + t] = (int)(0xFFFFFFFFu - (unsigned)(v & 0xFFFFFFFFu));
    }
}

// ---------------------------------------------------------------------------
// Kernel 2 (fused): one warp per output row.
//   warps [0, MROWS)        : merged row  (267 floats, unaligned dst -> scalar)
//   warps [MROWS, TOTROWS)  : cf row (256 floats, float4 both sides) + ca row
// ---------------------------------------------------------------------------
__global__ __launch_bounds__(256) void gather_kernel(
    const float* __restrict__ inst,   // BS,NA,ED
    const float* __restrict__ anch,   // BS,NA,AD
    const float* __restrict__ cfeat,  // BS,NT,ED
    const float* __restrict__ canch,  // BS,NT,AD
    float* __restrict__ merged,       // BS,NA,MD
    float* __restrict__ cf,           // BS,NT,ED
    float* __restrict__ ca)           // BS,NT,AD
{
    const int w    = (int)((blockIdx.x * blockDim.x + threadIdx.x) >> 5);
    const int lane = threadIdx.x & 31;
    if (w >= TOTROWS) return;

    if (w < MROWS) {
        // ----- merged row -----
        const int b = w / NA;
        const int s = g_src[w];
        const float* srcF;
        const float* srcA;
        if (s >= 0) {
            const size_t r = (size_t)b * NA + (unsigned)s;
            srcF = inst + r * ED;
            srcA = anch + r * AD;
        } else {
            const size_t r = (size_t)b * NT + (unsigned)(-s - 1);
            srcF = cfeat + r * ED;
            srcA = canch + r * AD;
        }
        float* dst = merged + (size_t)w * MD;
        #pragma unroll
        for (int c = 0; c < ED; c += 32) dst[c + lane] = srcF[c + lane];
        if (lane < AD) dst[ED + lane] = srcA[lane];
    } else {
        // ----- cf + ca row -----
        const int q = w - MROWS;          // b*NT + j
        const int b = q / NT;
        const int i = g_idx2[q];
        const int s = g_src[b * NA + i];
        const float4* srcF;
        const float*  srcA;
        if (s >= 0) {
            const size_t r = (size_t)b * NA + (unsigned)s;
            srcF = (const float4*)(inst + r * ED);
            srcA = anch + r * AD;
        } else {
            const size_t r = (size_t)b * NT + (unsigned)(-s - 1);
            srcF = (const float4*)(cfeat + r * ED);
            srcA = canch + r * AD;
        }
        float4* dstF = (float4*)(cf + (size_t)q * ED);
        dstF[lane]      = srcF[lane];
        dstF[lane + 32] = srcF[lane + 32];
        if (lane < AD) ca[(size_t)q * AD + lane] = srcA[lane];
    }
}

// ---------------------------------------------------------------------------
extern "C" void kernel_launch(void* const* d_in, const int* in_sizes, int n_in,
                              void* d_out, int out_size)
{
    const float* inst  = (const float*)d_in[0];
    const float* anch  = (const float*)d_in[1];
    const float* conf  = (const float*)d_in[2];
    const float* cfeat = (const float*)d_in[3];
    const float* canch = (const float*)d_in[4];
    const float* prevc = (const float*)d_in[5];
    const void*  mask  = (const void*)d_in[6];

    float* out     = (float*)d_out;
    float* merged  = out;                                      // BS*NA*MD
    float* newconf = merged + (size_t)BS * NA * MD;            // BS*NT
    float* cf      = newconf + (size_t)BS * NT;                // BS*NT*ED
    float* ca      = cf + (size_t)BS * NT * ED;                // BS*NT*AD

    topk_kernel<<<BS, TPB_SORT>>>(conf, prevc, mask, newconf);

    const int warps_per_block = 256 / 32;
    const int blocks = (TOTROWS + warps_per_block - 1) / warps_per_block;
    gather_kernel<<<blocks, 256>>>(inst, anch, cfeat, canch, merged, cf, ca);
}

// round 5
// speedup vs baseline: 2.5330x; 1.4079x over previous
#include <cuda_runtime.h>
#include <math.h>
#include <float.h>

#define BS 64
#define NA 900
#define NT 600
#define ED 256
#define AD 11
#define NC 10
#define NSEL (NA - NT)          /* 300 */
#define MD  (ED + AD)           /* 267 */
#define SORTN 1024
#define CONF_DECAY 0.6f

#define MROWS (BS * NA)          /* 57600 merged rows  */
#define QROWS (BS * NT)          /* 38400 cf/ca rows   */
#define TOTROWS (MROWS + QROWS)  /* 96000 warps        */
#define ROWS_PER_B (NA + NT)     /* 1500 */

// Scratch (no device mallocs allowed)
__device__ int g_src[BS * NA];   // per (b,i): >=0 -> instance row s ; <0 -> cached row -(s+1)
__device__ int g_idx2[BS * NT];  // second top-k indices into 0..NA-1

// ---------------------------------------------------------------------------
// Dtype-agnostic mask read (bool may arrive as uint8 / int32 / float32)
// ---------------------------------------------------------------------------
__device__ __forceinline__ bool read_mask(const void* mp, int b) {
    const unsigned char* u8 = (const unsigned char*)mp;
    bool any_gt1 = false, nonmult4 = false;
    #pragma unroll
    for (int i = 0; i < 64; i++) {
        unsigned char v = u8[i];
        if (v > 1) any_gt1 = true;
        if (v != 0 && (i & 3) != 0) nonmult4 = true;
    }
    if (any_gt1)  return ((const float*)mp)[b] != 0.0f;
    if (nonmult4) return u8[b] != 0;
    return ((const int*)mp)[b] != 0;
}

// ---------------------------------------------------------------------------
// Order-preserving float<->uint + (key, idx) u64 packing. Descending u64 sort
// == descending key, ascending index on ties (jax.lax.top_k semantics).
// ---------------------------------------------------------------------------
__device__ __forceinline__ unsigned int ord_of_float(float f) {
    unsigned int u = __float_as_uint(f);
    return (u & 0x80000000u) ? ~u : (u | 0x80000000u);
}
__device__ __forceinline__ float float_of_ord(unsigned int o) {
    unsigned int u = (o & 0x80000000u) ? (o ^ 0x80000000u) : ~u;
    // note: expression above must not use ~u before init; rewritten below
    return __uint_as_float(u);
}
__device__ __forceinline__ float float_of_ord_fixed(unsigned int o) {
    unsigned int u = (o & 0x80000000u) ? (o & 0x7FFFFFFFu) : ~o;
    return __uint_as_float(u);
}
__device__ __forceinline__ unsigned long long pack_ki(float k, int idx) {
    return ((unsigned long long)ord_of_float(k) << 32)
         | (unsigned long long)(0xFFFFFFFFu - (unsigned)idx);
}
__device__ __forceinline__ int idx_of_pack(unsigned long long v) {
    return (int)(0xFFFFFFFFu - (unsigned)(v & 0xFFFFFFFFu));
}

// ---------------------------------------------------------------------------
// Kernel 1: 128 blocks. Block (2b+0): sort conf_max -> g_src (needs mask).
//           Block (2b+1): sort conf_c  -> newconf + g_idx2.
// Register-resident bitonic: shfl for j<32, double-buffered shared for j>=32.
// ---------------------------------------------------------------------------
__global__ __launch_bounds__(SORTN) void topk_kernel(
    const float* __restrict__ conf,      // BS,NA,NC
    const float* __restrict__ prevconf,  // BS,NT
    const void*  __restrict__ mask,      // BS (bool; dtype unknown)
    float* __restrict__ newconf_out)     // BS,NT
{
    __shared__ unsigned long long buf[2][SORTN];
    __shared__ int sel[NSEL];

    const int b    = blockIdx.x >> 1;
    const int role = blockIdx.x & 1;
    const int t    = threadIdx.x;

    // build key
    unsigned long long v = 0ULL;
    if (t < NA) {
        const float* p = conf + ((size_t)b * NA + t) * NC;
        float m = p[0];
        #pragma unroll
        for (int c = 1; c < NC; c++) m = fmaxf(m, p[c]);
        if (role == 0) {
            v = pack_ki(m, t);
        } else {
            float s = 1.0f / (1.0f + expf(-m));
            if (t < NT) s = fmaxf(prevconf[b * NT + t] * CONF_DECAY, s);
            v = pack_ki(s, t);
        }
    }

    // bitonic sort, descending, element-in-register
    int pb = 0;
    #pragma unroll
    for (int k = 2; k <= SORTN; k <<= 1) {
        #pragma unroll
        for (int j = k >> 1; j > 0; j >>= 1) {
            unsigned long long u;
            if (j >= 32) {
                buf[pb][t] = v;
                __syncthreads();
                u = buf[pb][t ^ j];
                pb ^= 1;
            } else {
                u = __shfl_xor_sync(0xFFFFFFFFu, v, j);
            }
            bool lower = ((t & j) == 0);
            bool descB = ((t & k) == 0);
            bool want_max = (lower == descB);
            v = want_max ? (v > u ? v : u) : (v < u ? v : u);
        }
    }
    __syncthreads();

    if (role == 0) {
        if (t < NSEL) sel[t] = idx_of_pack(v);
        __syncthreads();
        const bool m = read_mask(mask, b);
        if (t < NA) {
            int s;
            if (m) s = (t < NT) ? -(t + 1) : sel[t - NT];
            else   s = t;
            g_src[b * NA + t] = s;
        }
    } else {
        if (t < NT) {
            newconf_out[b * NT + t] = float_of_ord_fixed((unsigned)(v >> 32));
            g_idx2[b * NT + t] = idx_of_pack(v);
        }
    }
}

// ---------------------------------------------------------------------------
// Kernel 2 (fused gather): one warp per output row, batch-interleaved order so
// a batch's cf reads hit L2 right after its merged reads. Streaming stores.
//   per batch: 900 merged rows then 600 cf(+ca) rows.
// ---------------------------------------------------------------------------
__global__ __launch_bounds__(256) void gather_kernel(
    const float* __restrict__ inst,   // BS,NA,ED
    const float* __restrict__ anch,   // BS,NA,AD
    const float* __restrict__ cfeat,  // BS,NT,ED
    const float* __restrict__ canch,  // BS,NT,AD
    float* __restrict__ merged,       // BS,NA,MD
    float* __restrict__ cf,           // BS,NT,ED
    float* __restrict__ ca)           // BS,NT,AD
{
    const int w    = (int)((blockIdx.x * blockDim.x + threadIdx.x) >> 5);
    const int lane = threadIdx.x & 31;
    if (w >= TOTROWS) return;

    const int b = w / ROWS_PER_B;
    const int r = w - b * ROWS_PER_B;

    if (r < NA) {
        // ----- merged row -----
        const int row = b * NA + r;
        const int s = g_src[row];
        const float* srcF;
        const float* srcA;
        if (s >= 0) {
            const size_t rr = (size_t)b * NA + (unsigned)s;
            srcF = inst + rr * ED;
            srcA = anch + rr * AD;
        } else {
            const size_t rr = (size_t)b * NT + (unsigned)(-s - 1);
            srcF = cfeat + rr * ED;
            srcA = canch + rr * AD;
        }
        float* dst = merged + (size_t)row * MD;
        #pragma unroll
        for (int c = 0; c < ED; c += 32) __stcs(dst + c + lane, srcF[c + lane]);
        if (lane < AD) __stcs(dst + ED + lane, srcA[lane]);
    } else {
        // ----- cf + ca row -----
        const int q = b * NT + (r - NA);
        const int i = g_idx2[q];
        const int s = g_src[b * NA + i];
        const float4* srcF;
        const float*  srcA;
        if (s >= 0) {
            const size_t rr = (size_t)b * NA + (unsigned)s;
            srcF = (const float4*)(inst + rr * ED);
            srcA = anch + rr * AD;
        } else {
            const size_t rr = (size_t)b * NT + (unsigned)(-s - 1);
            srcF = (const float4*)(cfeat + rr * ED);
            srcA = canch + rr * AD;
        }
        float4* dstF = (float4*)(cf + (size_t)q * ED);
        __stcs(dstF + lane,      srcF[lane]);
        __stcs(dstF + lane + 32, srcF[lane + 32]);
        if (lane < AD) __stcs(ca + (size_t)q * AD + lane, srcA[lane]);
    }
}

// ---------------------------------------------------------------------------
extern "C" void kernel_launch(void* const* d_in, const int* in_sizes, int n_in,
                              void* d_out, int out_size)
{
    const float* inst  = (const float*)d_in[0];
    const float* anch  = (const float*)d_in[1];
    const float* conf  = (const float*)d_in[2];
    const float* cfeat = (const float*)d_in[3];
    const float* canch = (const float*)d_in[4];
    const float* prevc = (const float*)d_in[5];
    const void*  mask  = (const void*)d_in[6];

    float* out     = (float*)d_out;
    float* merged  = out;                                      // BS*NA*MD
    float* newconf = merged + (size_t)BS * NA * MD;            // BS*NT
    float* cf      = newconf + (size_t)BS * NT;                // BS*NT*ED
    float* ca      = cf + (size_t)BS * NT * ED;                // BS*NT*AD

    topk_kernel<<<2 * BS, SORTN>>>(conf, prevc, mask, newconf);

    const int warps_per_block = 256 / 32;
    const int blocks = (TOTROWS + warps_per_block - 1) / warps_per_block;
    gather_kernel<<<blocks, 256>>>(inst, anch, cfeat, canch, merged, cf, ca);
}

// round 6
// speedup vs baseline: 2.9064x; 1.1474x over previous
#include <cuda_runtime.h>
#include <math.h>
#include <float.h>

#define BS 64
#define NA 900
#define NT 600
#define ED 256
#define AD 11
#define NC 10
#define NSEL (NA - NT)          /* 300 */
#define MD  (ED + AD)           /* 267 */
#define SORTN 1024
#define TPB_TOPK 256            /* 4 elements per thread */
#define CONF_DECAY 0.6f

#define MROWS (BS * NA)          /* 57600 merged rows  */
#define QROWS (BS * NT)          /* 38400 cf/ca rows   */
#define TOTROWS (MROWS + QROWS)  /* 96000 rows         */
#define ROWS_PER_B (NA + NT)     /* 1500 */
#define PAIRS_PER_B (ROWS_PER_B / 2) /* 750 */
#define TOTPAIRS (BS * PAIRS_PER_B)  /* 48000 warps */

// Scratch (no device mallocs allowed)
__device__ int g_src[BS * NA];   // per (b,i): >=0 -> instance row s ; <0 -> cached row -(s+1)
__device__ int g_idx2[BS * NT];  // second top-k indices into 0..NA-1

// ---------------------------------------------------------------------------
// Dtype-agnostic mask read (bool may arrive as uint8 / int32 / float32)
// ---------------------------------------------------------------------------
__device__ __forceinline__ bool read_mask(const void* mp, int b) {
    const unsigned char* u8 = (const unsigned char*)mp;
    bool any_gt1 = false, nonmult4 = false;
    #pragma unroll
    for (int i = 0; i < 64; i++) {
        unsigned char v = u8[i];
        if (v > 1) any_gt1 = true;
        if (v != 0 && (i & 3) != 0) nonmult4 = true;
    }
    if (any_gt1)  return ((const float*)mp)[b] != 0.0f;
    if (nonmult4) return u8[b] != 0;
    return ((const int*)mp)[b] != 0;
}

// ---------------------------------------------------------------------------
// Order-preserving float<->uint + (key, idx) u64 packing. Descending u64 sort
// == descending key, ascending index on ties (jax.lax.top_k semantics).
// ---------------------------------------------------------------------------
__device__ __forceinline__ unsigned int ord_of_float(float f) {
    unsigned int u = __float_as_uint(f);
    return (u & 0x80000000u) ? ~u : (u | 0x80000000u);
}
__device__ __forceinline__ float float_of_ord(unsigned int o) {
    unsigned int u = (o & 0x80000000u) ? (o & 0x7FFFFFFFu) : ~o;
    return __uint_as_float(u);
}
__device__ __forceinline__ unsigned long long pack_ki(float k, int idx) {
    return ((unsigned long long)ord_of_float(k) << 32)
         | (unsigned long long)(0xFFFFFFFFu - (unsigned)idx);
}
__device__ __forceinline__ int idx_of_pack(unsigned long long v) {
    return (int)(0xFFFFFFFFu - (unsigned)(v & 0xFFFFFFFFu));
}

// ---------------------------------------------------------------------------
// Kernel 1: 128 blocks of 256 threads, 4 elements/thread bitonic sort.
//   Block (2b+0): sort conf_max          -> g_src (uses mask, top-300 "sel")
//   Block (2b+1): sort conf_c (sigmoid)  -> newconf + g_idx2 (top-600)
// Element i = t + 256*e. j<32: shfl. 32<=j<=128: shared. j>=256: intra-thread.
// ---------------------------------------------------------------------------
__global__ __launch_bounds__(TPB_TOPK) void topk_kernel(
    const float* __restrict__ conf,      // BS,NA,NC
    const float* __restrict__ prevconf,  // BS,NT
    const void*  __restrict__ mask,      // BS (bool; dtype unknown)
    float* __restrict__ newconf_out)     // BS,NT
{
    __shared__ unsigned long long buf[2][SORTN];
    __shared__ int sel[NSEL];

    const int b    = blockIdx.x >> 1;
    const int role = blockIdx.x & 1;
    const int t    = threadIdx.x;

    unsigned long long v[4];

    // build keys for elements t + 256e
    #pragma unroll
    for (int e = 0; e < 4; e++) {
        const int i = t + 256 * e;
        if (i < NA) {
            const float* p = conf + ((size_t)b * NA + i) * NC;
            float m = p[0];
            #pragma unroll
            for (int c = 1; c < NC; c++) m = fmaxf(m, p[c]);
            if (role == 0) {
                v[e] = pack_ki(m, i);
            } else {
                float s = 1.0f / (1.0f + expf(-m));
                if (i < NT) s = fmaxf(prevconf[b * NT + i] * CONF_DECAY, s);
                v[e] = pack_ki(s, i);
            }
        } else {
            v[e] = 0ULL;
        }
    }

    // bitonic sort, descending. keep_max = ((i&j)==0) == ((i&k)==0)
    int pb = 0;
    #pragma unroll
    for (int k = 2; k <= SORTN; k <<= 1) {
        #pragma unroll
        for (int j = k >> 1; j > 0; j >>= 1) {
            if (j >= 256) {
                // intra-thread: partner differs only in e bits
                const int jj = j >> 8;
                #pragma unroll
                for (int e = 0; e < 4; e++) {
                    if ((e & jj) == 0) {
                        const int ep = e | jj;
                        const int i  = t + 256 * e;
                        // i is the lower partner ((i&j)==0 by construction)
                        const bool desc = ((i & k) == 0);
                        unsigned long long lo = v[e], hi = v[ep];
                        unsigned long long mx = lo > hi ? lo : hi;
                        unsigned long long mn = lo > hi ? hi : lo;
                        v[e]  = desc ? mx : mn;
                        v[ep] = desc ? mn : mx;
                    }
                }
            } else if (j >= 32) {
                // cross-thread within block: shared double buffer
                #pragma unroll
                for (int e = 0; e < 4; e++) buf[pb][t + 256 * e] = v[e];
                __syncthreads();
                #pragma unroll
                for (int e = 0; e < 4; e++) {
                    const int i = t + 256 * e;
                    unsigned long long u = buf[pb][i ^ j];
                    const bool keep_max = (((i & j) == 0) == ((i & k) == 0));
                    v[e] = keep_max ? (v[e] > u ? v[e] : u)
                                    : (v[e] < u ? v[e] : u);
                }
                pb ^= 1;
            } else {
                // lane exchange
                #pragma unroll
                for (int e = 0; e < 4; e++) {
                    unsigned long long u = __shfl_xor_sync(0xFFFFFFFFu, v[e], j);
                    const int i = t + 256 * e;
                    const bool keep_max = (((i & j) == 0) == ((i & k) == 0));
                    v[e] = keep_max ? (v[e] > u ? v[e] : u)
                                    : (v[e] < u ? v[e] : u);
                }
            }
        }
    }

    // thread t holds sorted positions t, t+256, t+512, t+768 (descending)
    if (role == 0) {
        if (t < NSEL) sel[t] = idx_of_pack(v[0]);              // pos 0..255 need e=0
        if (t + 256 < NSEL) sel[t + 256] = idx_of_pack(v[1]);  // pos 256..299
        __syncthreads();
        const bool m = read_mask(mask, b);
        #pragma unroll
        for (int e = 0; e < 4; e++) {
            const int i = t + 256 * e;
            if (i < NA) {
                int s;
                if (m) s = (i < NT) ? -(i + 1) : sel[i - NT];
                else   s = i;
                g_src[b * NA + i] = s;
            }
        }
    } else {
        #pragma unroll
        for (int e = 0; e < 3; e++) {                          // pos < 600 -> e<=2
            const int p = t + 256 * e;
            if (p < NT) {
                newconf_out[b * NT + p] = float_of_ord((unsigned)(v[e] >> 32));
                g_idx2[b * NT + p] = idx_of_pack(v[e]);
            }
        }
    }
}

// ---------------------------------------------------------------------------
// Kernel 2 (fused gather): one warp per PAIR of rows, batch-interleaved order.
// Both rows of a pair are the same kind (merged boundary at 900 is even).
// Index loads issued up-front for both rows -> 2x chain-level MLP.
// ---------------------------------------------------------------------------
__global__ __launch_bounds__(256) void gather_kernel(
    const float* __restrict__ inst,   // BS,NA,ED
    const float* __restrict__ anch,   // BS,NA,AD
    const float* __restrict__ cfeat,  // BS,NT,ED
    const float* __restrict__ canch,  // BS,NT,AD
    float* __restrict__ merged,       // BS,NA,MD
    float* __restrict__ cf,           // BS,NT,ED
    float* __restrict__ ca)           // BS,NT,AD
{
    const int w    = (int)((blockIdx.x * blockDim.x + threadIdx.x) >> 5);
    const int lane = threadIdx.x & 31;
    if (w >= TOTPAIRS) return;

    const int b  = w / PAIRS_PER_B;
    const int pr = w - b * PAIRS_PER_B;
    const int r0 = 2 * pr;

    if (r0 < NA) {
        // ----- two merged rows -----
        const int2 ss = *(const int2*)(g_src + b * NA + r0);
        const float *srcF0, *srcA0, *srcF1, *srcA1;
        if (ss.x >= 0) { const size_t rr = (size_t)b * NA + (unsigned)ss.x;
                         srcF0 = inst + rr * ED;  srcA0 = anch + rr * AD; }
        else           { const size_t rr = (size_t)b * NT + (unsigned)(-ss.x - 1);
                         srcF0 = cfeat + rr * ED; srcA0 = canch + rr * AD; }
        if (ss.y >= 0) { const size_t rr = (size_t)b * NA + (unsigned)ss.y;
                         srcF1 = inst + rr * ED;  srcA1 = anch + rr * AD; }
        else           { const size_t rr = (size_t)b * NT + (unsigned)(-ss.y - 1);
                         srcF1 = cfeat + rr * ED; srcA1 = canch + rr * AD; }

        float f0[8], f1[8];
        #pragma unroll
        for (int c = 0; c < 8; c++) f0[c] = srcF0[c * 32 + lane];
        #pragma unroll
        for (int c = 0; c < 8; c++) f1[c] = srcF1[c * 32 + lane];
        float a0 = 0.f, a1 = 0.f;
        if (lane < AD) { a0 = srcA0[lane]; a1 = srcA1[lane]; }

        float* dst0 = merged + (size_t)(b * NA + r0) * MD;
        float* dst1 = dst0 + MD;
        #pragma unroll
        for (int c = 0; c < 8; c++) __stcs(dst0 + c * 32 + lane, f0[c]);
        if (lane < AD) __stcs(dst0 + ED + lane, a0);
        #pragma unroll
        for (int c = 0; c < 8; c++) __stcs(dst1 + c * 32 + lane, f1[c]);
        if (lane < AD) __stcs(dst1 + ED + lane, a1);
    } else {
        // ----- two cf (+ca) rows -----
        const int q0 = b * NT + (r0 - NA);
        const int2 ii = *(const int2*)(g_idx2 + q0);
        const int s0 = g_src[b * NA + ii.x];
        const int s1 = g_src[b * NA + ii.y];

        const float4 *srcF0, *srcF1;
        const float  *srcA0, *srcA1;
        if (s0 >= 0) { const size_t rr = (size_t)b * NA + (unsigned)s0;
                       srcF0 = (const float4*)(inst + rr * ED);  srcA0 = anch + rr * AD; }
        else         { const size_t rr = (size_t)b * NT + (unsigned)(-s0 - 1);
                       srcF0 = (const float4*)(cfeat + rr * ED); srcA0 = canch + rr * AD; }
        if (s1 >= 0) { const size_t rr = (size_t)b * NA + (unsigned)s1;
                       srcF1 = (const float4*)(inst + rr * ED);  srcA1 = anch + rr * AD; }
        else         { const size_t rr = (size_t)b * NT + (unsigned)(-s1 - 1);
                       srcF1 = (const float4*)(cfeat + rr * ED); srcA1 = canch + rr * AD; }

        float4 v00 = srcF0[lane], v01 = srcF0[lane + 32];
        float4 v10 = srcF1[lane], v11 = srcF1[lane + 32];
        float a0 = 0.f, a1 = 0.f;
        if (lane < AD) { a0 = srcA0[lane]; a1 = srcA1[lane]; }

        float4* dst0 = (float4*)(cf + (size_t)q0 * ED);
        float4* dst1 = dst0 + (ED / 4);
        __stcs(dst0 + lane,      v00);
        __stcs(dst0 + lane + 32, v01);
        __stcs(dst1 + lane,      v10);
        __stcs(dst1 + lane + 32, v11);
        if (lane < AD) {
            __stcs(ca + (size_t)q0 * AD + lane, a0);
            __stcs(ca + (size_t)(q0 + 1) * AD + lane, a1);
        }
    }
}

// ---------------------------------------------------------------------------
extern "C" void kernel_launch(void* const* d_in, const int* in_sizes, int n_in,
                              void* d_out, int out_size)
{
    const float* inst  = (const float*)d_in[0];
    const float* anch  = (const float*)d_in[1];
    const float* conf  = (const float*)d_in[2];
    const float* cfeat = (const float*)d_in[3];
    const float* canch = (const float*)d_in[4];
    const float* prevc = (const float*)d_in[5];
    const void*  mask  = (const void*)d_in[6];

    float* out     = (float*)d_out;
    float* merged  = out;                                      // BS*NA*MD
    float* newconf = merged + (size_t)BS * NA * MD;            // BS*NT
    float* cf      = newconf + (size_t)BS * NT;                // BS*NT*ED
    float* ca      = cf + (size_t)BS * NT * ED;                // BS*NT*AD

    topk_kernel<<<2 * BS, TPB_TOPK>>>(conf, prevc, mask, newconf);

    const int warps_per_block = 256 / 32;
    const int blocks = (TOTPAIRS + warps_per_block - 1) / warps_per_block;
    gather_kernel<<<blocks, 256>>>(inst, anch, cfeat, canch, merged, cf, ca);
}

// round 7
// speedup vs baseline: 3.0024x; 1.0330x over previous
#include <cuda_runtime.h>
#include <math.h>
#include <float.h>

#define BS 64
#define NA 900
#define NT 600
#define ED 256
#define AD 11
#define NC 10
#define NSEL (NA - NT)          /* 300 */
#define MD  (ED + AD)           /* 267 */
#define SORTN 1024
#define TPB_TOPK 512            /* 2 elements per thread */
#define CONF_DECAY 0.6f

#define MQUADS_PER_B (NA / 4)    /* 225 */
#define QQUADS_PER_B (NT / 4)    /* 150 */
#define QUADS_PER_B (MQUADS_PER_B + QQUADS_PER_B) /* 375 */
#define TOTQUADS (BS * QUADS_PER_B)               /* 24000 warps */

// Scratch (no device mallocs allowed)
__device__ int g_src[BS * NA];   // per (b,i): >=0 -> instance row s ; <0 -> cached row -(s+1)
__device__ int g_idx2[BS * NT];  // second top-k indices into 0..NA-1

// ---------------------------------------------------------------------------
// Dtype-agnostic mask read (bool may arrive as uint8 / int32 / float32)
// ---------------------------------------------------------------------------
__device__ __forceinline__ bool read_mask(const void* mp, int b) {
    const unsigned char* u8 = (const unsigned char*)mp;
    bool any_gt1 = false, nonmult4 = false;
    #pragma unroll
    for (int i = 0; i < 64; i++) {
        unsigned char v = u8[i];
        if (v > 1) any_gt1 = true;
        if (v != 0 && (i & 3) != 0) nonmult4 = true;
    }
    if (any_gt1)  return ((const float*)mp)[b] != 0.0f;
    if (nonmult4) return u8[b] != 0;
    return ((const int*)mp)[b] != 0;
}

// ---------------------------------------------------------------------------
// Order-preserving float<->uint + (key, idx) u64 packing. Descending u64 sort
// == descending key, ascending index on ties (jax.lax.top_k semantics).
// ---------------------------------------------------------------------------
__device__ __forceinline__ unsigned int ord_of_float(float f) {
    unsigned int u = __float_as_uint(f);
    return (u & 0x80000000u) ? ~u : (u | 0x80000000u);
}
__device__ __forceinline__ float float_of_ord(unsigned int o) {
    unsigned int u = (o & 0x80000000u) ? (o & 0x7FFFFFFFu) : ~o;
    return __uint_as_float(u);
}
__device__ __forceinline__ unsigned long long pack_ki(float k, int idx) {
    return ((unsigned long long)ord_of_float(k) << 32)
         | (unsigned long long)(0xFFFFFFFFu - (unsigned)idx);
}
__device__ __forceinline__ int idx_of_pack(unsigned long long v) {
    return (int)(0xFFFFFFFFu - (unsigned)(v & 0xFFFFFFFFu));
}

// ---------------------------------------------------------------------------
// Kernel 1: 128 blocks of 512 threads, 2 elements/thread bitonic sort.
//   Block (2b+0): sort conf_max          -> g_src (uses mask, top-300 "sel")
//   Block (2b+1): sort conf_c (sigmoid)  -> newconf + g_idx2 (top-600)
// Element i = t + 512*e. j<32: shfl. 32<=j<=256: shared. j=512: intra-thread.
// ---------------------------------------------------------------------------
__global__ __launch_bounds__(TPB_TOPK) void topk_kernel(
    const float* __restrict__ conf,      // BS,NA,NC
    const float* __restrict__ prevconf,  // BS,NT
    const void*  __restrict__ mask,      // BS (bool; dtype unknown)
    float* __restrict__ newconf_out)     // BS,NT
{
    __shared__ unsigned long long buf[2][SORTN];
    __shared__ int sel[NSEL];

    const int b    = blockIdx.x >> 1;
    const int role = blockIdx.x & 1;
    const int t    = threadIdx.x;

    unsigned long long v[2];

    // build keys for elements t + 512e
    #pragma unroll
    for (int e = 0; e < 2; e++) {
        const int i = t + 512 * e;
        if (i < NA) {
            const float* p = conf + ((size_t)b * NA + i) * NC;
            float m = p[0];
            #pragma unroll
            for (int c = 1; c < NC; c++) m = fmaxf(m, p[c]);
            if (role == 0) {
                v[e] = pack_ki(m, i);
            } else {
                float s = 1.0f / (1.0f + expf(-m));
                if (i < NT) s = fmaxf(prevconf[b * NT + i] * CONF_DECAY, s);
                v[e] = pack_ki(s, i);
            }
        } else {
            v[e] = 0ULL;
        }
    }

    // bitonic sort, descending. keep_max = ((i&j)==0) == ((i&k)==0)
    int pb = 0;
    #pragma unroll
    for (int k = 2; k <= SORTN; k <<= 1) {
        #pragma unroll
        for (int j = k >> 1; j > 0; j >>= 1) {
            if (j >= 512) {
                // intra-thread swap between e=0 (lower) and e=1. k==1024 here,
                // so (i & k)==0 always -> descending -> keep max in e=0.
                unsigned long long lo = v[0], hi = v[1];
                v[0] = lo > hi ? lo : hi;
                v[1] = lo > hi ? hi : lo;
            } else if (j >= 32) {
                #pragma unroll
                for (int e = 0; e < 2; e++) buf[pb][t + 512 * e] = v[e];
                __syncthreads();
                #pragma unroll
                for (int e = 0; e < 2; e++) {
                    const int i = t + 512 * e;
                    unsigned long long u = buf[pb][i ^ j];
                    const bool keep_max = (((i & j) == 0) == ((i & k) == 0));
                    v[e] = keep_max ? (v[e] > u ? v[e] : u)
                                    : (v[e] < u ? v[e] : u);
                }
                pb ^= 1;
            } else {
                #pragma unroll
                for (int e = 0; e < 2; e++) {
                    unsigned long long u = __shfl_xor_sync(0xFFFFFFFFu, v[e], j);
                    const int i = t + 512 * e;
                    const bool keep_max = (((i & j) == 0) == ((i & k) == 0));
                    v[e] = keep_max ? (v[e] > u ? v[e] : u)
                                    : (v[e] < u ? v[e] : u);
                }
            }
        }
    }

    // thread t holds sorted positions t and t+512 (descending)
    if (role == 0) {
        if (t < NSEL) sel[t] = idx_of_pack(v[0]);   // positions 0..299 all in e=0
        __syncthreads();
        const bool m = read_mask(mask, b);
        #pragma unroll
        for (int e = 0; e < 2; e++) {
            const int i = t + 512 * e;
            if (i < NA) {
                int s;
                if (m) s = (i < NT) ? -(i + 1) : sel[i - NT];
                else   s = i;
                g_src[b * NA + i] = s;
            }
        }
    } else {
        // positions 0..511 in e=0, 512..599 in e=1 (t<88)
        newconf_out[b * NT + t] = float_of_ord((unsigned)(v[0] >> 32));
        g_idx2[b * NT + t] = idx_of_pack(v[0]);
        if (t < NT - 512) {
            const int p = t + 512;
            newconf_out[b * NT + p] = float_of_ord((unsigned)(v[1] >> 32));
            g_idx2[b * NT + p] = idx_of_pack(v[1]);
        }
    }
}

// ---------------------------------------------------------------------------
// Kernel 2 (fused gather): one warp per QUAD of rows, batch-interleaved order.
// All 4 rows of a quad are the same kind (900 and 600 both divisible by 4).
// Index loads (int4) issued up-front -> 4x chain-level MLP per warp.
// ---------------------------------------------------------------------------
__global__ __launch_bounds__(256) void gather_kernel(
    const float* __restrict__ inst,   // BS,NA,ED
    const float* __restrict__ anch,   // BS,NA,AD
    const float* __restrict__ cfeat,  // BS,NT,ED
    const float* __restrict__ canch,  // BS,NT,AD
    float* __restrict__ merged,       // BS,NA,MD
    float* __restrict__ cf,           // BS,NT,ED
    float* __restrict__ ca)           // BS,NT,AD
{
    const int w    = (int)((blockIdx.x * blockDim.x + threadIdx.x) >> 5);
    const int lane = threadIdx.x & 31;
    if (w >= TOTQUADS) return;

    const int b  = w / QUADS_PER_B;
    const int qr = w - b * QUADS_PER_B;

    if (qr < MQUADS_PER_B) {
        // ----- four merged rows -----
        const int r0 = 4 * qr;
        const int4 ss = *(const int4*)(g_src + b * NA + r0);
        int sv[4] = {ss.x, ss.y, ss.z, ss.w};

        const float* srcF[4];
        const float* srcA[4];
        #pragma unroll
        for (int r = 0; r < 4; r++) {
            if (sv[r] >= 0) {
                const size_t rr = (size_t)b * NA + (unsigned)sv[r];
                srcF[r] = inst + rr * ED;
                srcA[r] = anch + rr * AD;
            } else {
                const size_t rr = (size_t)b * NT + (unsigned)(-sv[r] - 1);
                srcF[r] = cfeat + rr * ED;
                srcA[r] = canch + rr * AD;
            }
        }

        float f[4][8];
        float a[4];
        #pragma unroll
        for (int r = 0; r < 4; r++)
            #pragma unroll
            for (int c = 0; c < 8; c++)
                f[r][c] = srcF[r][c * 32 + lane];
        #pragma unroll
        for (int r = 0; r < 4; r++)
            a[r] = (lane < AD) ? srcA[r][lane] : 0.0f;

        float* dst = merged + (size_t)(b * NA + r0) * MD;
        #pragma unroll
        for (int r = 0; r < 4; r++) {
            #pragma unroll
            for (int c = 0; c < 8; c++)
                __stcs(dst + (size_t)r * MD + c * 32 + lane, f[r][c]);
            if (lane < AD) __stcs(dst + (size_t)r * MD + ED + lane, a[r]);
        }
    } else {
        // ----- four cf (+ca) rows -----
        const int q0 = b * NT + 4 * (qr - MQUADS_PER_B);
        const int4 ii = *(const int4*)(g_idx2 + q0);
        int iv[4] = {ii.x, ii.y, ii.z, ii.w};

        int sv[4];
        #pragma unroll
        for (int r = 0; r < 4; r++) sv[r] = g_src[b * NA + iv[r]];

        const float4* srcF[4];
        const float*  srcA[4];
        #pragma unroll
        for (int r = 0; r < 4; r++) {
            if (sv[r] >= 0) {
                const size_t rr = (size_t)b * NA + (unsigned)sv[r];
                srcF[r] = (const float4*)(inst + rr * ED);
                srcA[r] = anch + rr * AD;
            } else {
                const size_t rr = (size_t)b * NT + (unsigned)(-sv[r] - 1);
                srcF[r] = (const float4*)(cfeat + rr * ED);
                srcA[r] = canch + rr * AD;
            }
        }

        float4 vv[4][2];
        float  a[4];
        #pragma unroll
        for (int r = 0; r < 4; r++) {
            vv[r][0] = srcF[r][lane];
            vv[r][1] = srcF[r][lane + 32];
        }
        #pragma unroll
        for (int r = 0; r < 4; r++)
            a[r] = (lane < AD) ? srcA[r][lane] : 0.0f;

        float4* dstF = (float4*)(cf + (size_t)q0 * ED);
        #pragma unroll
        for (int r = 0; r < 4; r++) {
            __stcs(dstF + r * (ED / 4) + lane,      vv[r][0]);
            __stcs(dstF + r * (ED / 4) + lane + 32, vv[r][1]);
        }
        if (lane < AD) {
            #pragma unroll
            for (int r = 0; r < 4; r++)
                __stcs(ca + (size_t)(q0 + r) * AD + lane, a[r]);
        }
    }
}

// ---------------------------------------------------------------------------
extern "C" void kernel_launch(void* const* d_in, const int* in_sizes, int n_in,
                              void* d_out, int out_size)
{
    const float* inst  = (const float*)d_in[0];
    const float* anch  = (const float*)d_in[1];
    const float* conf  = (const float*)d_in[2];
    const float* cfeat = (const float*)d_in[3];
    const float* canch = (const float*)d_in[4];
    const float* prevc = (const float*)d_in[5];
    const void*  mask  = (const void*)d_in[6];

    float* out     = (float*)d_out;
    float* merged  = out;                                      // BS*NA*MD
    float* newconf = merged + (size_t)BS * NA * MD;            // BS*NT
    float* cf      = newconf + (size_t)BS * NT;                // BS*NT*ED
    float* ca      = cf + (size_t)BS * NT * ED;                // BS*NT*AD

    topk_kernel<<<2 * BS, TPB_TOPK>>>(conf, prevc, mask, newconf);

    const int warps_per_block = 256 / 32;
    const int blocks = (TOTQUADS + warps_per_block - 1) / warps_per_block;
    gather_kernel<<<blocks, 256>>>(inst, anch, cfeat, canch, merged, cf, ca);
}